// round 4
// baseline (speedup 1.0000x reference)
#include <cuda_runtime.h>
#include <cuda_bf16.h>
#include <cstdint>
#include <cstddef>

#define DEVFN __device__ __forceinline__

constexpr int TOK = 3072, DDIM = 2048, FDIM = 8192;
constexpr int WELEM = FDIM * DDIM;
constexpr int BM = 128, BN = 128, BK = 64;
constexpr int KITERS = DDIM / BK;            // 32
constexpr int TILE_B = BM * BK;              // 8192 bytes per operand tile
constexpr int STAGE_B = 3 * TILE_B;          // A + Wg + Wu = 24576
constexpr int STAGES = 4;
constexpr int SMEM_GEMM = STAGES * STAGE_B;  // 98304

// scratch (device globals; no allocation allowed)
__device__ float d_part[3 * 512];
__device__ float d_wsinv[3];
__device__ uint8_t d_qa[(size_t)TOK * DDIM];          // packed fragment order
__device__ float d_ainv[TOK];
__device__ uint8_t d_qg[(size_t)FDIM * DDIM];         // packed fragment order
__device__ uint8_t d_qu[(size_t)FDIM * DDIM];
__device__ float d_v[FDIM];
__device__ float d_h[(size_t)TOK * FDIM];
__device__ float d_tok[TOK];
__device__ float d_pool[24];

DEVFN float wsum(float v) {
    #pragma unroll
    for (int o = 16; o; o >>= 1) v += __shfl_xor_sync(~0u, v, o);
    return v;
}
DEVFN float wmax(float v) {
    #pragma unroll
    for (int o = 16; o; o >>= 1) v = fmaxf(v, __shfl_xor_sync(~0u, v, o));
    return v;
}
DEVFN int8_t tern(float w, float ws) {
    return (int8_t)(int)fminf(fmaxf(rintf(w * ws), -1.f), 1.f);
}

// ---------------- K1: |W| partial sums ----------------
__global__ void wred_kernel(const float* __restrict__ Wg, const float* __restrict__ Wu,
                            const float* __restrict__ Wd) {
    int y = blockIdx.y;
    const float4* W = (const float4*)(y == 0 ? Wg : (y == 1 ? Wu : Wd));
    float s = 0.f;
    for (int i = blockIdx.x * 256 + threadIdx.x; i < WELEM / 4; i += 512 * 256) {
        float4 w = W[i];
        s += fabsf(w.x) + fabsf(w.y) + fabsf(w.z) + fabsf(w.w);
    }
    s = wsum(s);
    __shared__ float rs[8];
    if ((threadIdx.x & 31) == 0) rs[threadIdx.x >> 5] = s;
    __syncthreads();
    if (threadIdx.x == 0) {
        float S = 0.f;
        #pragma unroll
        for (int k = 0; k < 8; k++) S += rs[k];
        d_part[y * 512 + blockIdx.x] = S;
    }
}

// ---------------- K2: finalize weight scales ----------------
__global__ void fin_kernel() {
    int y = blockIdx.x, tid = threadIdx.x;
    double s = 0.0;
    for (int i = tid; i < 512; i += 256) s += (double)d_part[y * 512 + i];
    #pragma unroll
    for (int o = 16; o; o >>= 1) s += __shfl_xor_sync(~0u, s, o);
    __shared__ double ds[8];
    if ((tid & 31) == 0) ds[tid >> 5] = s;
    __syncthreads();
    if (tid == 0) {
        double S = 0.0;
        #pragma unroll
        for (int k = 0; k < 8; k++) S += ds[k];
        d_wsinv[y] = (float)fmax(S / (double)WELEM, 1e-5);
    }
}

// A packed address for element (m, k-group g = k/4), byte k%4 within u32.
DEVFN size_t a_addr(int m, int g) {
    int kb = g >> 4;
    int i4 = (m & 127) >> 4;
    int s = (g >> 3) & 1;
    int t = ((m & 7) << 2) | (g & 3);
    int r = ((m >> 3) & 1) | (((g >> 2) & 1) << 1);
    return ((size_t)((m >> 7) * 32 + kb) << 13) + (((s * 8 + i4) * 32 + t) << 4) + r * 4;
}
// B packed address for (n, g)
DEVFN size_t b_addr(int n, int g) {
    int kb = g >> 4;
    int j = (n & 127) >> 3;
    int s = (g >> 3) & 1;
    int t = ((n & 7) << 2) | (g & 3);
    int r = (g >> 2) & 1;
    return ((size_t)((n >> 7) * 32 + kb) << 13) + (((s * 16 + j) * 32 + t) << 3) + r * 4;
}

// ---------------- K3: activation quant -> packed int8 ----------------
__global__ void act_kernel(const float* __restrict__ x) {
    int m = blockIdx.x, tid = threadIdx.x;
    const float4* row = (const float4*)(x + (size_t)m * DDIM);
    float mx = 0.f;
    for (int i = tid; i < 512; i += 256) {
        float4 w = row[i];
        mx = fmaxf(mx, fmaxf(fmaxf(fabsf(w.x), fabsf(w.y)), fmaxf(fabsf(w.z), fabsf(w.w))));
    }
    mx = wmax(mx);
    __shared__ float rm[8], smv;
    if ((tid & 31) == 0) rm[tid >> 5] = mx;
    __syncthreads();
    if (tid == 0) {
        float M = 0.f;
        #pragma unroll
        for (int k = 0; k < 8; k++) M = fmaxf(M, rm[k]);
        smv = fmaxf(M, 1e-5f);
    }
    __syncthreads();
    float scale = 127.0f / smv;
    for (int g = tid; g < 512; g += 256) {
        float4 w = row[g];
        int q0 = (int)fminf(fmaxf(rintf(w.x * scale), -128.f), 127.f);
        int q1 = (int)fminf(fmaxf(rintf(w.y * scale), -128.f), 127.f);
        int q2 = (int)fminf(fmaxf(rintf(w.z * scale), -128.f), 127.f);
        int q3 = (int)fminf(fmaxf(rintf(w.w * scale), -128.f), 127.f);
        uint32_t p = (uint32_t)(uint8_t)q0 | ((uint32_t)(uint8_t)q1 << 8) |
                     ((uint32_t)(uint8_t)q2 << 16) | ((uint32_t)(uint8_t)q3 << 24);
        *(uint32_t*)(d_qa + a_addr(m, g)) = p;
    }
    if (tid == 0) d_ainv[m] = smv / 127.0f;
}

// ---------------- K4: ternary quant Wg,Wu -> packed int8; zero d_v ----------------
__global__ void qw_kernel(const float* __restrict__ Wg, const float* __restrict__ Wu) {
    if (blockIdx.y == 0 && blockIdx.x < 32) d_v[blockIdx.x * 256 + threadIdx.x] = 0.f;
    const float4* src = (const float4*)(blockIdx.y ? Wu : Wg);
    uint8_t* dst = blockIdx.y ? d_qu : d_qg;
    float ws = 1.0f / d_wsinv[blockIdx.y];
    int stride = gridDim.x * 256;
    for (int i = blockIdx.x * 256 + threadIdx.x; i < WELEM / 4; i += stride) {
        int n = i >> 9, g = i & 511;
        float4 w = src[i];
        uint32_t p = (uint32_t)(uint8_t)tern(w.x, ws) |
                     ((uint32_t)(uint8_t)tern(w.y, ws) << 8) |
                     ((uint32_t)(uint8_t)tern(w.z, ws) << 16) |
                     ((uint32_t)(uint8_t)tern(w.w, ws) << 24);
        *(uint32_t*)(dst + b_addr(n, g)) = p;
    }
}

// ---------------- K5: v[f] = sum_d ternary(Wd[d,f]) ----------------
__global__ void vsum_kernel(const float* __restrict__ Wd) {
    int f = blockIdx.x * 256 + threadIdx.x;
    int d0 = blockIdx.y * 128;
    float ws = 1.0f / d_wsinv[2];
    float s = 0.f;
    #pragma unroll 4
    for (int d = 0; d < 128; d++)
        s += fminf(fmaxf(rintf(Wd[(size_t)(d0 + d) * FDIM + f] * ws), -1.f), 1.f);
    atomicAdd(&d_v[f], s);  // integer-valued floats: order-independent
}

// ---------------- K6: fused int8 double-GEMM + silu*mul epilogue ----------------
DEVFN void mma_s8(int* c, const uint32_t* a, uint32_t b0, uint32_t b1) {
    asm volatile(
        "mma.sync.aligned.m16n8k32.row.col.s32.s8.s8.s32 "
        "{%0,%1,%2,%3}, {%4,%5,%6,%7}, {%8,%9}, {%0,%1,%2,%3};"
        : "+r"(c[0]), "+r"(c[1]), "+r"(c[2]), "+r"(c[3])
        : "r"(a[0]), "r"(a[1]), "r"(a[2]), "r"(a[3]), "r"(b0), "r"(b1));
}

__global__ void __launch_bounds__(256, 1) gemm_kernel() {
    extern __shared__ uint8_t smem[];
    int tid = threadIdx.x, lane = tid & 31, wid = tid >> 5;
    int wm = wid & 3, wn = wid >> 2;       // 4 (m) x 2 (n) warps
    int mb = blockIdx.y, nb = blockIdx.x;

    const uint8_t* gA = d_qa + ((size_t)mb << 18);   // mb*32*8192
    const uint8_t* gG = d_qg + ((size_t)nb << 18);
    const uint8_t* gU = d_qu + ((size_t)nb << 18);

    int cg[2][8][4], cu[2][8][4];
    #pragma unroll
    for (int a = 0; a < 2; a++)
        #pragma unroll
        for (int b = 0; b < 8; b++)
            #pragma unroll
            for (int c = 0; c < 4; c++) { cg[a][b][c] = 0; cu[a][b][c] = 0; }

    // prologue: load stages 0..2
    #pragma unroll
    for (int st = 0; st < 3; st++) {
        uint8_t* base = smem + st * STAGE_B;
        const uint8_t* srcs[3] = { gA + (size_t)st * TILE_B, gG + (size_t)st * TILE_B,
                                   gU + (size_t)st * TILE_B };
        for (int c = tid; c < 1536; c += 256) {
            uint32_t dst_s;
            asm("{ .reg .u64 t; cvta.to.shared.u64 t, %1; cvt.u32.u64 %0, t; }"
                : "=r"(dst_s) : "l"(base + (c >> 9) * TILE_B + (c & 511) * 16));
            asm volatile("cp.async.cg.shared.global [%0], [%1], 16;"
                         :: "r"(dst_s), "l"(srcs[c >> 9] + (c & 511) * 16));
        }
        asm volatile("cp.async.commit_group;" ::: "memory");
    }

    for (int kb = 0; kb < KITERS; kb++) {
        if (kb < 30)      asm volatile("cp.async.wait_group 2;" ::: "memory");
        else if (kb == 30) asm volatile("cp.async.wait_group 1;" ::: "memory");
        else               asm volatile("cp.async.wait_group 0;" ::: "memory");
        __syncthreads();

        // prefetch stage kb+3
        if (kb + 3 < KITERS) {
            int st = (kb + 3) & 3;
            uint8_t* base = smem + st * STAGE_B;
            size_t off = (size_t)(kb + 3) * TILE_B;
            const uint8_t* srcs[3] = { gA + off, gG + off, gU + off };
            for (int c = tid; c < 1536; c += 256) {
                uint32_t dst_s;
                asm("{ .reg .u64 t; cvta.to.shared.u64 t, %1; cvt.u32.u64 %0, t; }"
                    : "=r"(dst_s) : "l"(base + (c >> 9) * TILE_B + (c & 511) * 16));
                asm volatile("cp.async.cg.shared.global [%0], [%1], 16;"
                             :: "r"(dst_s), "l"(srcs[c >> 9] + (c & 511) * 16));
            }
            asm volatile("cp.async.commit_group;" ::: "memory");
        }

        const uint8_t* sA = smem + (kb & 3) * STAGE_B;
        const uint8_t* sG = sA + TILE_B;
        const uint8_t* sU = sA + 2 * TILE_B;

        #pragma unroll
        for (int s = 0; s < 2; s++) {
            uint32_t af[2][4];
            #pragma unroll
            for (int mt = 0; mt < 2; mt++) {
                uint4 v = *(const uint4*)(sA + (((s * 8 + 2 * wm + mt) * 32 + lane) << 4));
                af[mt][0] = v.x; af[mt][1] = v.y; af[mt][2] = v.z; af[mt][3] = v.w;
            }
            #pragma unroll
            for (int j8 = 0; j8 < 8; j8++) {
                int j = wn * 8 + j8;
                uint2 bg = *(const uint2*)(sG + (((s * 16 + j) * 32 + lane) << 3));
                uint2 bu = *(const uint2*)(sU + (((s * 16 + j) * 32 + lane) << 3));
                #pragma unroll
                for (int mt = 0; mt < 2; mt++) {
                    mma_s8(cg[mt][j8], af[mt], bg.x, bg.y);
                    mma_s8(cu[mt][j8], af[mt], bu.x, bu.y);
                }
            }
        }
    }

    // epilogue: h = silu(g*sg) * (u*su) -> d_h
    float wsg = d_wsinv[0], wsu = d_wsinv[1];
    #pragma unroll
    for (int mt = 0; mt < 2; mt++) {
        #pragma unroll
        for (int h2 = 0; h2 < 2; h2++) {
            int row = mb * 128 + (2 * wm + mt) * 16 + h2 * 8 + (lane >> 2);
            float ai = d_ainv[row];
            float sg = wsg * ai, su = wsu * ai;
            float* drow = d_h + (size_t)row * FDIM;
            #pragma unroll
            for (int j8 = 0; j8 < 8; j8++) {
                int n0 = nb * 128 + (wn * 8 + j8) * 8 + 2 * (lane & 3);
                float g0 = (float)cg[mt][j8][h2 * 2] * sg;
                float g1 = (float)cg[mt][j8][h2 * 2 + 1] * sg;
                float u0 = (float)cu[mt][j8][h2 * 2] * su;
                float u1 = (float)cu[mt][j8][h2 * 2 + 1] * su;
                float2 o;
                o.x = g0 / (1.f + __expf(-g0)) * u0;
                o.y = g1 / (1.f + __expf(-g1)) * u1;
                *(float2*)(drow + n0) = o;
            }
        }
    }
}

// ---------------- K7: rmsnorm + act quant + dot with v ----------------
__global__ void hnorm_kernel(const float* __restrict__ lnw) {
    __shared__ float row[FDIM];
    __shared__ float red[8];
    __shared__ float bval;
    int t = blockIdx.x, tid = threadIdx.x;
    const float* src = d_h + (size_t)t * FDIM;
    float ss = 0.f;
    for (int i = tid; i < FDIM; i += 256) { float v = src[i]; row[i] = v; ss += v * v; }
    ss = wsum(ss);
    if ((tid & 31) == 0) red[tid >> 5] = ss;
    __syncthreads();
    if (tid == 0) {
        float S = 0.f;
        #pragma unroll
        for (int k = 0; k < 8; k++) S += red[k];
        bval = rsqrtf(S / (float)FDIM + 1e-6f);
    }
    __syncthreads();
    float rn = bval, mx = 0.f;
    for (int i = tid; i < FDIM; i += 256) {
        float v = row[i] * rn * lnw[i];
        row[i] = v;
        mx = fmaxf(mx, fabsf(v));
    }
    mx = wmax(mx);
    if ((tid & 31) == 0) red[tid >> 5] = mx;
    __syncthreads();
    if (tid == 0) {
        float M = 0.f;
        #pragma unroll
        for (int k = 0; k < 8; k++) M = fmaxf(M, red[k]);
        bval = fmaxf(M, 1e-5f);
    }
    __syncthreads();
    float clipv = bval, scale = 127.f / clipv, dot = 0.f;
    for (int i = tid; i < FDIM; i += 256) {
        float q = fminf(fmaxf(rintf(row[i] * scale), -128.f), 127.f);
        dot += q * d_v[i];
    }
    dot = wsum(dot);
    if ((tid & 31) == 0) red[tid >> 5] = dot;
    __syncthreads();
    if (tid == 0) {
        float S = 0.f;
        #pragma unroll
        for (int k = 0; k < 8; k++) S += red[k];
        d_tok[t] = S * (clipv / 127.f) * d_wsinv[2];
    }
}

// ---------------- K8: pool ----------------
__global__ void pool_kernel() {
    int g = blockIdx.x, tid = threadIdx.x;
    float v = d_tok[g * 128 + tid];
    v = wsum(v);
    __shared__ float r[4];
    if ((tid & 31) == 0) r[tid >> 5] = v;
    __syncthreads();
    if (tid == 0) d_pool[g] = (r[0] + r[1] + r[2] + r[3]) * (1.0f / (128.f * 2048.f));
}

// ---------------- K9: classifier ----------------
__global__ void cls_kernel(const float* __restrict__ W, const float* __restrict__ b,
                           float* __restrict__ out) {
    int i = blockIdx.x * 256 + threadIdx.x;
    if (i < 8000) {
        int bb = i / 1000, n = i % 1000;
        float s = b[n];
        #pragma unroll
        for (int c = 0; c < 3; c++) s += d_pool[bb * 3 + c] * W[n * 3 + c];
        out[i] = s;
    }
}

extern "C" void kernel_launch(void* const* d_in, const int* in_sizes, int n_in,
                              void* d_out, int out_size) {
    const float* x    = (const float*)d_in[0];
    const float* Wg   = (const float*)d_in[1];
    const float* Wu   = (const float*)d_in[2];
    const float* Wd   = (const float*)d_in[3];
    const float* lnw  = (const float*)d_in[4];
    const float* clsW = (const float*)d_in[5];
    const float* clsb = (const float*)d_in[6];
    float* out = (float*)d_out;

    cudaFuncSetAttribute(gemm_kernel, cudaFuncAttributeMaxDynamicSharedMemorySize, SMEM_GEMM);

    wred_kernel<<<dim3(512, 3), 256>>>(Wg, Wu, Wd);
    fin_kernel<<<3, 256>>>();
    act_kernel<<<TOK, 256>>>(x);
    qw_kernel<<<dim3(4096, 2), 256>>>(Wg, Wu);
    vsum_kernel<<<dim3(32, 16), 256>>>(Wd);
    gemm_kernel<<<dim3(FDIM / BN, TOK / BM), 256, SMEM_GEMM>>>();
    hnorm_kernel<<<TOK, 256>>>(lnw);
    pool_kernel<<<24, 128>>>();
    cls_kernel<<<32, 256>>>(clsW, clsb, out);
}

// round 5
// speedup vs baseline: 1.0145x; 1.0145x over previous
#include <cuda_runtime.h>
#include <cuda_bf16.h>
#include <cstdint>
#include <cstddef>

#define DEVFN __device__ __forceinline__

constexpr int TOK = 3072, DDIM = 2048, FDIM = 8192;
constexpr int WELEM = FDIM * DDIM;
constexpr int BM = 128, BN = 128, BK = 64;
constexpr int KITERS = DDIM / BK;            // 32
constexpr int TILE_B = BM * BK;              // 8192 B
constexpr int STAGE_B = 3 * TILE_B;          // 24576
constexpr int STAGES = 4;
constexpr int SMEM_GEMM = STAGES * STAGE_B;  // 98304

__device__ float d_part[3 * 512];
__device__ float d_wsinv[3];
__device__ uint8_t d_qa[(size_t)TOK * DDIM];
__device__ float d_ainv[TOK];
__device__ uint8_t d_qg[(size_t)FDIM * DDIM];
__device__ uint8_t d_qu[(size_t)FDIM * DDIM];
__device__ float d_v[FDIM];
__device__ float d_h[(size_t)TOK * FDIM];
__device__ float d_tok[TOK];
__device__ float d_pool[24];

DEVFN float wsum(float v) {
    #pragma unroll
    for (int o = 16; o; o >>= 1) v += __shfl_xor_sync(~0u, v, o);
    return v;
}
DEVFN float wmax(float v) {
    #pragma unroll
    for (int o = 16; o; o >>= 1) v = fmaxf(v, __shfl_xor_sync(~0u, v, o));
    return v;
}
DEVFN int8_t tern(float w, float ws) {
    return (int8_t)(int)fminf(fmaxf(rintf(w * ws), -1.f), 1.f);
}

// ---------------- K0: |W| partial sums ----------------
__global__ void wred_kernel(const float* __restrict__ Wg, const float* __restrict__ Wu,
                            const float* __restrict__ Wd) {
    int y = blockIdx.y;
    const float4* W = (const float4*)(y == 0 ? Wg : (y == 1 ? Wu : Wd));
    float s = 0.f;
    for (int i = blockIdx.x * 256 + threadIdx.x; i < WELEM / 4; i += 512 * 256) {
        float4 w = W[i];
        s += fabsf(w.x) + fabsf(w.y) + fabsf(w.z) + fabsf(w.w);
    }
    s = wsum(s);
    __shared__ float rs[8];
    if ((threadIdx.x & 31) == 0) rs[threadIdx.x >> 5] = s;
    __syncthreads();
    if (threadIdx.x == 0) {
        float S = 0.f;
        #pragma unroll
        for (int k = 0; k < 8; k++) S += rs[k];
        d_part[y * 512 + blockIdx.x] = S;
    }
}

// packed fragment addressing
DEVFN size_t a_addr(int m, int g) {
    int kb = g >> 4;
    int i4 = (m & 127) >> 4;
    int s = (g >> 3) & 1;
    int t = ((m & 7) << 2) | (g & 3);
    int r = ((m >> 3) & 1) | (((g >> 2) & 1) << 1);
    return ((size_t)((m >> 7) * 32 + kb) << 13) + (((s * 8 + i4) * 32 + t) << 4) + r * 4;
}
DEVFN size_t b_addr(int n, int g) {
    int kb = g >> 4;
    int j = (n & 127) >> 3;
    int s = (g >> 3) & 1;
    int t = ((n & 7) << 2) | (g & 3);
    int r = (g >> 2) & 1;
    return ((size_t)((n >> 7) * 32 + kb) << 13) + (((s * 16 + j) * 32 + t) << 3) + r * 4;
}

// ---------------- K1: ternary quant Wg,Wu (scale computed inline); zero d_v ----------------
__global__ void qw_kernel() {}  // placeholder name stability
__global__ void qw2_kernel(const float* __restrict__ Wg, const float* __restrict__ Wu) {
    int y = blockIdx.y, tid = threadIdx.x;
    // inline scale: reduce the 512 partials for this weight
    float ps = 0.f;
    #pragma unroll
    for (int k = 0; k < 2; k++) ps += d_part[y * 512 + tid * 2 + k];
    ps = wsum(ps);
    __shared__ float rs[8];
    __shared__ float sws;
    if ((tid & 31) == 0) rs[tid >> 5] = ps;
    __syncthreads();
    if (tid == 0) {
        float S = 0.f;
        #pragma unroll
        for (int k = 0; k < 8; k++) S += rs[k];
        float wm = fmaxf(S / (float)WELEM, 1e-5f);
        sws = wm;
        if (blockIdx.x == 0) d_wsinv[y] = wm;
    }
    __syncthreads();
    if (y == 0 && blockIdx.x < 32) d_v[blockIdx.x * 256 + tid] = 0.f;
    const float4* src = (const float4*)(y ? Wu : Wg);
    uint8_t* dst = y ? d_qu : d_qg;
    float ws = 1.0f / sws;
    int stride = gridDim.x * 256;
    for (int i = blockIdx.x * 256 + tid; i < WELEM / 4; i += stride) {
        int n = i >> 9, g = i & 511;
        float4 w = src[i];
        uint32_t p = (uint32_t)(uint8_t)tern(w.x, ws) |
                     ((uint32_t)(uint8_t)tern(w.y, ws) << 8) |
                     ((uint32_t)(uint8_t)tern(w.z, ws) << 16) |
                     ((uint32_t)(uint8_t)tern(w.w, ws) << 24);
        *(uint32_t*)(dst + b_addr(n, g)) = p;
    }
}

// ---------------- K2: activation quant -> packed int8 ----------------
__global__ void act_kernel(const float* __restrict__ x) {
    int m = blockIdx.x, tid = threadIdx.x;
    const float4* row = (const float4*)(x + (size_t)m * DDIM);
    float mx = 0.f;
    for (int i = tid; i < 512; i += 256) {
        float4 w = row[i];
        mx = fmaxf(mx, fmaxf(fmaxf(fabsf(w.x), fabsf(w.y)), fmaxf(fabsf(w.z), fabsf(w.w))));
    }
    mx = wmax(mx);
    __shared__ float rm[8], smv;
    if ((tid & 31) == 0) rm[tid >> 5] = mx;
    __syncthreads();
    if (tid == 0) {
        float M = 0.f;
        #pragma unroll
        for (int k = 0; k < 8; k++) M = fmaxf(M, rm[k]);
        smv = fmaxf(M, 1e-5f);
    }
    __syncthreads();
    float scale = 127.0f / smv;
    for (int g = tid; g < 512; g += 256) {
        float4 w = row[g];
        int q0 = (int)fminf(fmaxf(rintf(w.x * scale), -128.f), 127.f);
        int q1 = (int)fminf(fmaxf(rintf(w.y * scale), -128.f), 127.f);
        int q2 = (int)fminf(fmaxf(rintf(w.z * scale), -128.f), 127.f);
        int q3 = (int)fminf(fmaxf(rintf(w.w * scale), -128.f), 127.f);
        uint32_t p = (uint32_t)(uint8_t)q0 | ((uint32_t)(uint8_t)q1 << 8) |
                     ((uint32_t)(uint8_t)q2 << 16) | ((uint32_t)(uint8_t)q3 << 24);
        *(uint32_t*)(d_qa + a_addr(m, g)) = p;
    }
    if (tid == 0) d_ainv[m] = smv / 127.0f;
}

// ---------------- K3: fused int8 double-GEMM (512 threads, 16 warps) ----------------
DEVFN void mma_s8(int* c, const uint32_t* a, uint32_t b0, uint32_t b1) {
    asm volatile(
        "mma.sync.aligned.m16n8k32.row.col.s32.s8.s8.s32 "
        "{%0,%1,%2,%3}, {%4,%5,%6,%7}, {%8,%9}, {%0,%1,%2,%3};"
        : "+r"(c[0]), "+r"(c[1]), "+r"(c[2]), "+r"(c[3])
        : "r"(a[0]), "r"(a[1]), "r"(a[2]), "r"(a[3]), "r"(b0), "r"(b1));
}

DEVFN void stage_copy(uint8_t* smem, int st, const uint8_t* gA, const uint8_t* gG,
                      const uint8_t* gU, int kb, int tid) {
    uint8_t* base = smem + st * STAGE_B;
    size_t koff = (size_t)kb * TILE_B + (size_t)(tid << 4);
    const uint8_t* s0 = gA + koff;
    const uint8_t* s1 = gG + koff;
    const uint8_t* s2 = gU + koff;
    uint32_t d0, d1, d2;
    asm("{ .reg .u64 t; cvta.to.shared.u64 t, %1; cvt.u32.u64 %0, t; }"
        : "=r"(d0) : "l"(base + (tid << 4)));
    d1 = d0 + TILE_B; d2 = d0 + 2 * TILE_B;
    asm volatile("cp.async.cg.shared.global [%0], [%1], 16;" :: "r"(d0), "l"(s0));
    asm volatile("cp.async.cg.shared.global [%0], [%1], 16;" :: "r"(d1), "l"(s1));
    asm volatile("cp.async.cg.shared.global [%0], [%1], 16;" :: "r"(d2), "l"(s2));
}

__global__ void __launch_bounds__(512, 1) gemm_kernel() {
    extern __shared__ uint8_t smem[];
    int tid = threadIdx.x, lane = tid & 31, wid = tid >> 5;
    int wm = wid & 3, wn = wid >> 2;      // 4 (m) x 4 (n) warps
    int mb = blockIdx.y, nb = blockIdx.x;

    const uint8_t* gA = d_qa + ((size_t)mb << 18);
    const uint8_t* gG = d_qg + ((size_t)nb << 18);
    const uint8_t* gU = d_qu + ((size_t)nb << 18);

    int cg[2][4][4], cu[2][4][4];
    #pragma unroll
    for (int a = 0; a < 2; a++)
        #pragma unroll
        for (int b = 0; b < 4; b++)
            #pragma unroll
            for (int c = 0; c < 4; c++) { cg[a][b][c] = 0; cu[a][b][c] = 0; }

    #pragma unroll
    for (int st = 0; st < 3; st++) {
        stage_copy(smem, st, gA, gG, gU, st, tid);
        asm volatile("cp.async.commit_group;" ::: "memory");
    }

    for (int kb = 0; kb < KITERS; kb++) {
        if (kb < 30)       asm volatile("cp.async.wait_group 2;" ::: "memory");
        else if (kb == 30) asm volatile("cp.async.wait_group 1;" ::: "memory");
        else               asm volatile("cp.async.wait_group 0;" ::: "memory");
        __syncthreads();

        if (kb + 3 < KITERS) {
            stage_copy(smem, (kb + 3) & 3, gA, gG, gU, kb + 3, tid);
            asm volatile("cp.async.commit_group;" ::: "memory");
        }

        const uint8_t* sA = smem + (kb & 3) * STAGE_B;
        const uint8_t* sG = sA + TILE_B;
        const uint8_t* sU = sA + 2 * TILE_B;

        #pragma unroll
        for (int s = 0; s < 2; s++) {
            uint32_t af[2][4];
            #pragma unroll
            for (int mt = 0; mt < 2; mt++) {
                uint4 v = *(const uint4*)(sA + (((s * 8 + 2 * wm + mt) * 32 + lane) << 4));
                af[mt][0] = v.x; af[mt][1] = v.y; af[mt][2] = v.z; af[mt][3] = v.w;
            }
            #pragma unroll
            for (int j8 = 0; j8 < 4; j8++) {
                int j = wn * 4 + j8;
                uint2 bg = *(const uint2*)(sG + (((s * 16 + j) * 32 + lane) << 3));
                uint2 bu = *(const uint2*)(sU + (((s * 16 + j) * 32 + lane) << 3));
                #pragma unroll
                for (int mt = 0; mt < 2; mt++) {
                    mma_s8(cg[mt][j8], af[mt], bg.x, bg.y);
                    mma_s8(cu[mt][j8], af[mt], bu.x, bu.y);
                }
            }
        }
    }

    float wsg = d_wsinv[0], wsu = d_wsinv[1];
    #pragma unroll
    for (int mt = 0; mt < 2; mt++) {
        #pragma unroll
        for (int h2 = 0; h2 < 2; h2++) {
            int row = mb * 128 + (2 * wm + mt) * 16 + h2 * 8 + (lane >> 2);
            float ai = d_ainv[row];
            float sg = wsg * ai, su = wsu * ai;
            float* drow = d_h + (size_t)row * FDIM;
            #pragma unroll
            for (int j8 = 0; j8 < 4; j8++) {
                int n0 = nb * 128 + (wn * 4 + j8) * 8 + 2 * (lane & 3);
                float g0 = (float)cg[mt][j8][h2 * 2] * sg;
                float g1 = (float)cg[mt][j8][h2 * 2 + 1] * sg;
                float u0 = (float)cu[mt][j8][h2 * 2] * su;
                float u1 = (float)cu[mt][j8][h2 * 2 + 1] * su;
                float2 o;
                o.x = g0 / (1.f + __expf(-g0)) * u0;
                o.y = g1 / (1.f + __expf(-g1)) * u1;
                *(float2*)(drow + n0) = o;
            }
        }
    }
}

// ---------------- K4: finalize Wd scale only ----------------
__global__ void fin2_kernel() {
    int tid = threadIdx.x;
    double s = 0.0;
    for (int i = tid; i < 512; i += 256) s += (double)d_part[2 * 512 + i];
    #pragma unroll
    for (int o = 16; o; o >>= 1) s += __shfl_xor_sync(~0u, s, o);
    __shared__ double ds[8];
    if ((tid & 31) == 0) ds[tid >> 5] = s;
    __syncthreads();
    if (tid == 0) {
        double S = 0.0;
        #pragma unroll
        for (int k = 0; k < 8; k++) S += ds[k];
        d_wsinv[2] = (float)fmax(S / (double)WELEM, 1e-5);
    }
}

// ---------------- K5: v[f] = sum_d ternary(Wd[d,f]) ----------------
__global__ void vsum_kernel(const float* __restrict__ Wd) {
    int f = blockIdx.x * 256 + threadIdx.x;
    int d0 = blockIdx.y * 128;
    float ws = 1.0f / d_wsinv[2];
    float s = 0.f;
    #pragma unroll 4
    for (int d = 0; d < 128; d++)
        s += fminf(fmaxf(rintf(Wd[(size_t)(d0 + d) * FDIM + f] * ws), -1.f), 1.f);
    atomicAdd(&d_v[f], s);
}

// ---------------- K6: rmsnorm + act quant + dot with v ----------------
__global__ void hnorm_kernel(const float* __restrict__ lnw) {
    __shared__ float row[FDIM];
    __shared__ float red[8];
    __shared__ float bval;
    int t = blockIdx.x, tid = threadIdx.x;
    const float* src = d_h + (size_t)t * FDIM;
    float ss = 0.f;
    for (int i = tid; i < FDIM; i += 256) { float v = src[i]; row[i] = v; ss += v * v; }
    ss = wsum(ss);
    if ((tid & 31) == 0) red[tid >> 5] = ss;
    __syncthreads();
    if (tid == 0) {
        float S = 0.f;
        #pragma unroll
        for (int k = 0; k < 8; k++) S += red[k];
        bval = rsqrtf(S / (float)FDIM + 1e-6f);
    }
    __syncthreads();
    float rn = bval, mx = 0.f;
    for (int i = tid; i < FDIM; i += 256) {
        float v = row[i] * rn * lnw[i];
        row[i] = v;
        mx = fmaxf(mx, fabsf(v));
    }
    mx = wmax(mx);
    if ((tid & 31) == 0) red[tid >> 5] = mx;
    __syncthreads();
    if (tid == 0) {
        float M = 0.f;
        #pragma unroll
        for (int k = 0; k < 8; k++) M = fmaxf(M, red[k]);
        bval = fmaxf(M, 1e-5f);
    }
    __syncthreads();
    float clipv = bval, scale = 127.f / clipv, dot = 0.f;
    for (int i = tid; i < FDIM; i += 256) {
        float q = fminf(fmaxf(rintf(row[i] * scale), -128.f), 127.f);
        dot += q * d_v[i];
    }
    dot = wsum(dot);
    if ((tid & 31) == 0) red[tid >> 5] = dot;
    __syncthreads();
    if (tid == 0) {
        float S = 0.f;
        #pragma unroll
        for (int k = 0; k < 8; k++) S += red[k];
        d_tok[t] = S * (clipv / 127.f) * d_wsinv[2];
    }
}

// ---------------- K7: pool ----------------
__global__ void pool_kernel() {
    int g = blockIdx.x, tid = threadIdx.x;
    float v = d_tok[g * 128 + tid];
    v = wsum(v);
    __shared__ float r[4];
    if ((tid & 31) == 0) r[tid >> 5] = v;
    __syncthreads();
    if (tid == 0) d_pool[g] = (r[0] + r[1] + r[2] + r[3]) * (1.0f / (128.f * 2048.f));
}

// ---------------- K8: classifier ----------------
__global__ void cls_kernel(const float* __restrict__ W, const float* __restrict__ b,
                           float* __restrict__ out) {
    int i = blockIdx.x * 256 + threadIdx.x;
    if (i < 8000) {
        int bb = i / 1000, n = i % 1000;
        float s = b[n];
        #pragma unroll
        for (int c = 0; c < 3; c++) s += d_pool[bb * 3 + c] * W[n * 3 + c];
        out[i] = s;
    }
}

extern "C" void kernel_launch(void* const* d_in, const int* in_sizes, int n_in,
                              void* d_out, int out_size) {
    const float* x    = (const float*)d_in[0];
    const float* Wg   = (const float*)d_in[1];
    const float* Wu   = (const float*)d_in[2];
    const float* Wd   = (const float*)d_in[3];
    const float* lnw  = (const float*)d_in[4];
    const float* clsW = (const float*)d_in[5];
    const float* clsb = (const float*)d_in[6];
    float* out = (float*)d_out;

    cudaFuncSetAttribute(gemm_kernel, cudaFuncAttributeMaxDynamicSharedMemorySize, SMEM_GEMM);

    wred_kernel<<<dim3(512, 3), 256>>>(Wg, Wu, Wd);
    qw2_kernel<<<dim3(4096, 2), 256>>>(Wg, Wu);
    act_kernel<<<TOK, 256>>>(x);
    gemm_kernel<<<dim3(FDIM / BN, TOK / BM), 512, SMEM_GEMM>>>();
    fin2_kernel<<<1, 256>>>();
    vsum_kernel<<<dim3(32, 16), 256>>>(Wd);
    hnorm_kernel<<<TOK, 256>>>(lnw);
    pool_kernel<<<24, 128>>>();
    cls_kernel<<<32, 256>>>(clsW, clsb, out);
}

// round 6
// speedup vs baseline: 1.4409x; 1.4203x over previous
#include <cuda_runtime.h>
#include <cuda_bf16.h>
#include <cstdint>
#include <cstddef>

#define DEVFN __device__ __forceinline__

constexpr int TOK = 3072, DDIM = 2048, FDIM = 8192;
constexpr int WELEM = FDIM * DDIM;
constexpr int BM = 128, BN = 128, BK = 64;
constexpr int KITERS = DDIM / BK;            // 32
constexpr int TILE_B = BM * BK;              // 8192 B
constexpr int STAGE_B = 3 * TILE_B;          // 24576
constexpr int STAGES = 4;
constexpr int SMEM_GEMM = STAGES * STAGE_B;  // 98304

__device__ float d_part[3 * 512];
__device__ float d_wsinv[3];
__device__ uint8_t d_qa[(size_t)TOK * DDIM];
__device__ float d_ainv[TOK];
__device__ uint8_t d_qg[(size_t)FDIM * DDIM];
__device__ uint8_t d_qu[(size_t)FDIM * DDIM];
__device__ float d_v[FDIM];
__device__ float d_h[(size_t)TOK * FDIM];
__device__ float d_tok[TOK];
__device__ float d_pool[24];

DEVFN float wsum(float v) {
    #pragma unroll
    for (int o = 16; o; o >>= 1) v += __shfl_xor_sync(~0u, v, o);
    return v;
}
DEVFN float wmax(float v) {
    #pragma unroll
    for (int o = 16; o; o >>= 1) v = fmaxf(v, __shfl_xor_sync(~0u, v, o));
    return v;
}
DEVFN int8_t tern(float w, float ws) {
    return (int8_t)(int)fminf(fmaxf(rintf(w * ws), -1.f), 1.f);
}

// ---------------- K0: |W| partial sums ----------------
__global__ void wred_kernel(const float* __restrict__ Wg, const float* __restrict__ Wu,
                            const float* __restrict__ Wd) {
    int y = blockIdx.y;
    const float4* W = (const float4*)(y == 0 ? Wg : (y == 1 ? Wu : Wd));
    float s = 0.f;
    for (int i = blockIdx.x * 256 + threadIdx.x; i < WELEM / 4; i += 512 * 256) {
        float4 w = W[i];
        s += fabsf(w.x) + fabsf(w.y) + fabsf(w.z) + fabsf(w.w);
    }
    s = wsum(s);
    __shared__ float rs[8];
    if ((threadIdx.x & 31) == 0) rs[threadIdx.x >> 5] = s;
    __syncthreads();
    if (threadIdx.x == 0) {
        float S = 0.f;
        #pragma unroll
        for (int k = 0; k < 8; k++) S += rs[k];
        d_part[y * 512 + blockIdx.x] = S;
    }
}

// packed fragment addressing
DEVFN size_t a_addr(int m, int g) {
    int kb = g >> 4;
    int i4 = (m & 127) >> 4;
    int s = (g >> 3) & 1;
    int t = ((m & 7) << 2) | (g & 3);
    int r = ((m >> 3) & 1) | (((g >> 2) & 1) << 1);
    return ((size_t)((m >> 7) * 32 + kb) << 13) + (((s * 8 + i4) * 32 + t) << 4) + r * 4;
}
DEVFN size_t b_addr(int n, int g) {
    int kb = g >> 4;
    int j = (n & 127) >> 3;
    int s = (g >> 3) & 1;
    int t = ((n & 7) << 2) | (g & 3);
    int r = (g >> 2) & 1;
    return ((size_t)((n >> 7) * 32 + kb) << 13) + (((s * 16 + j) * 32 + t) << 3) + r * 4;
}

// ---------------- K1: ternary quant Wg,Wu (inline scale); zero d_v ----------------
__global__ void qw2_kernel(const float* __restrict__ Wg, const float* __restrict__ Wu) {
    int y = blockIdx.y, tid = threadIdx.x;
    float ps = 0.f;
    #pragma unroll
    for (int k = 0; k < 2; k++) ps += d_part[y * 512 + tid * 2 + k];
    ps = wsum(ps);
    __shared__ float rs[8];
    __shared__ float sws;
    if ((tid & 31) == 0) rs[tid >> 5] = ps;
    __syncthreads();
    if (tid == 0) {
        float S = 0.f;
        #pragma unroll
        for (int k = 0; k < 8; k++) S += rs[k];
        float wm = fmaxf(S / (float)WELEM, 1e-5f);
        sws = wm;
        if (blockIdx.x == 0) d_wsinv[y] = wm;
    }
    __syncthreads();
    if (y == 0 && blockIdx.x < 32) d_v[blockIdx.x * 256 + tid] = 0.f;
    const float4* src = (const float4*)(y ? Wu : Wg);
    uint8_t* dst = y ? d_qu : d_qg;
    float ws = 1.0f / sws;
    int stride = gridDim.x * 256;
    for (int i = blockIdx.x * 256 + tid; i < WELEM / 4; i += stride) {
        int n = i >> 9, g = i & 511;
        float4 w = src[i];
        uint32_t p = (uint32_t)(uint8_t)tern(w.x, ws) |
                     ((uint32_t)(uint8_t)tern(w.y, ws) << 8) |
                     ((uint32_t)(uint8_t)tern(w.z, ws) << 16) |
                     ((uint32_t)(uint8_t)tern(w.w, ws) << 24);
        *(uint32_t*)(dst + b_addr(n, g)) = p;
    }
}

// ---------------- K2: activation quant -> packed int8 ----------------
__global__ void act_kernel(const float* __restrict__ x) {
    int m = blockIdx.x, tid = threadIdx.x;
    const float4* row = (const float4*)(x + (size_t)m * DDIM);
    float mx = 0.f;
    for (int i = tid; i < 512; i += 256) {
        float4 w = row[i];
        mx = fmaxf(mx, fmaxf(fmaxf(fabsf(w.x), fabsf(w.y)), fmaxf(fabsf(w.z), fabsf(w.w))));
    }
    mx = wmax(mx);
    __shared__ float rm[8], smv;
    if ((tid & 31) == 0) rm[tid >> 5] = mx;
    __syncthreads();
    if (tid == 0) {
        float M = 0.f;
        #pragma unroll
        for (int k = 0; k < 8; k++) M = fmaxf(M, rm[k]);
        smv = fmaxf(M, 1e-5f);
    }
    __syncthreads();
    float scale = 127.0f / smv;
    for (int g = tid; g < 512; g += 256) {
        float4 w = row[g];
        int q0 = (int)fminf(fmaxf(rintf(w.x * scale), -128.f), 127.f);
        int q1 = (int)fminf(fmaxf(rintf(w.y * scale), -128.f), 127.f);
        int q2 = (int)fminf(fmaxf(rintf(w.z * scale), -128.f), 127.f);
        int q3 = (int)fminf(fmaxf(rintf(w.w * scale), -128.f), 127.f);
        uint32_t p = (uint32_t)(uint8_t)q0 | ((uint32_t)(uint8_t)q1 << 8) |
                     ((uint32_t)(uint8_t)q2 << 16) | ((uint32_t)(uint8_t)q3 << 24);
        *(uint32_t*)(d_qa + a_addr(m, g)) = p;
    }
    if (tid == 0) d_ainv[m] = smv / 127.0f;
}

// ---------------- K3: hybrid tensor+dp4a double-GEMM ----------------
DEVFN void mma_s8(int* c, const uint32_t* a, uint32_t b0, uint32_t b1) {
    asm volatile(
        "mma.sync.aligned.m16n8k32.row.col.s32.s8.s8.s32 "
        "{%0,%1,%2,%3}, {%4,%5,%6,%7}, {%8,%9}, {%0,%1,%2,%3};"
        : "+r"(c[0]), "+r"(c[1]), "+r"(c[2]), "+r"(c[3])
        : "r"(a[0]), "r"(a[1]), "r"(a[2]), "r"(a[3]), "r"(b0), "r"(b1));
}

DEVFN void stage_copy(uint8_t* smem, int st, const uint8_t* gA, const uint8_t* gG,
                      const uint8_t* gU, int kb, int tid) {
    uint8_t* base = smem + st * STAGE_B;
    size_t koff = (size_t)kb * TILE_B + (size_t)(tid << 4);
    uint32_t d0;
    asm("{ .reg .u64 t; cvta.to.shared.u64 t, %1; cvt.u32.u64 %0, t; }"
        : "=r"(d0) : "l"(base + (tid << 4)));
    asm volatile("cp.async.cg.shared.global [%0], [%1], 16;" :: "r"(d0), "l"(gA + koff));
    asm volatile("cp.async.cg.shared.global [%0], [%1], 16;" :: "r"(d0 + TILE_B), "l"(gG + koff));
    asm volatile("cp.async.cg.shared.global [%0], [%1], 16;" :: "r"(d0 + 2 * TILE_B), "l"(gU + koff));
}

__global__ void __launch_bounds__(512, 1) gemm_kernel() {
    extern __shared__ uint8_t smem[];
    int tid = threadIdx.x, lane = tid & 31, wid = tid >> 5;
    int mb = blockIdx.y, nb = blockIdx.x;

    const uint8_t* gA = d_qa + ((size_t)mb << 18);
    const uint8_t* gG = d_qg + ((size_t)nb << 18);
    const uint8_t* gU = d_qu + ((size_t)nb << 18);

    // shared accumulator file: tensor warps use cg=acc[0..31], cu=acc[32..63];
    // dp4a warps use acc[i*8+j]
    int acc[64];
    #pragma unroll
    for (int k = 0; k < 64; k++) acc[k] = 0;

    // tensor warp coords (wid 0..7): 4m x 2n, n in [0,64)
    int wm = wid & 3, wn = (wid >> 2) & 1;
    // dp4a warp coords (wid 8..15): mat (G/U) x 4 m-blocks, n in [64,128)
    int dw = wid - 8;
    int mat = dw & 1, mblk = dw >> 1;
    int mrow = lane >> 3, ncol = lane & 7;

    #pragma unroll
    for (int st = 0; st < 3; st++) {
        stage_copy(smem, st, gA, gG, gU, st, tid);
        asm volatile("cp.async.commit_group;" ::: "memory");
    }

    for (int kb = 0; kb < KITERS; kb++) {
        if (kb < 30)       asm volatile("cp.async.wait_group 2;" ::: "memory");
        else if (kb == 30) asm volatile("cp.async.wait_group 1;" ::: "memory");
        else               asm volatile("cp.async.wait_group 0;" ::: "memory");
        __syncthreads();

        if (kb + 3 < KITERS) {
            stage_copy(smem, (kb + 3) & 3, gA, gG, gU, kb + 3, tid);
            asm volatile("cp.async.commit_group;" ::: "memory");
        }

        const uint8_t* sA = smem + (kb & 3) * STAGE_B;
        const uint8_t* sG = sA + TILE_B;
        const uint8_t* sU = sA + 2 * TILE_B;

        if (wid < 8) {
            // -------- tensor path: n in [0,64) --------
            #pragma unroll
            for (int s = 0; s < 2; s++) {
                uint32_t af[2][4];
                #pragma unroll
                for (int mt = 0; mt < 2; mt++) {
                    uint4 v = *(const uint4*)(sA + (((s * 8 + 2 * wm + mt) * 32 + lane) << 4));
                    af[mt][0] = v.x; af[mt][1] = v.y; af[mt][2] = v.z; af[mt][3] = v.w;
                }
                #pragma unroll
                for (int j8 = 0; j8 < 4; j8++) {
                    int j = wn * 4 + j8;
                    uint2 bg = *(const uint2*)(sG + (((s * 16 + j) * 32 + lane) << 3));
                    uint2 bu = *(const uint2*)(sU + (((s * 16 + j) * 32 + lane) << 3));
                    #pragma unroll
                    for (int mt = 0; mt < 2; mt++) {
                        mma_s8(&acc[(mt * 4 + j8) * 4], af[mt], bg.x, bg.y);
                        mma_s8(&acc[32 + (mt * 4 + j8) * 4], af[mt], bu.x, bu.y);
                    }
                }
            }
        } else {
            // -------- dp4a path: n in [64,128) --------
            const uint8_t* sB = mat ? sU : sG;
            int i4 = mblk * 2 + (mrow >> 1);
            int r0 = (mrow & 1) * 4;
            #pragma unroll
            for (int s = 0; s < 2; s++) {
                #pragma unroll
                for (int g2 = 0; g2 < 4; g2++) {
                    int a0 = (((s * 8 + i4) * 32 + g2) << 4) + r0;
                    int b0 = (((s * 16 + 8) * 32 + ncol * 4 + g2) << 3);
                    int av0[8], av1[8], bv0[8], bv1[8];
                    #pragma unroll
                    for (int i = 0; i < 8; i++) {
                        const uint8_t* p = sA + a0 + (i << 6);
                        av0[i] = *(const int*)p;
                        av1[i] = *(const int*)(p + 8);
                    }
                    #pragma unroll
                    for (int j = 0; j < 8; j++) {
                        int2 b2 = *(const int2*)(sB + b0 + (j << 8));
                        bv0[j] = b2.x; bv1[j] = b2.y;
                    }
                    #pragma unroll
                    for (int i = 0; i < 8; i++)
                        #pragma unroll
                        for (int j = 0; j < 8; j++)
                            acc[i * 8 + j] = __dp4a(av1[i], bv1[j],
                                             __dp4a(av0[i], bv0[j], acc[i * 8 + j]));
                }
            }
        }
    }

    __syncthreads();
    // dp4a G-warps publish their int sums for the combine
    int* sx = (int*)smem;
    if (wid >= 8 && mat == 0) {
        #pragma unroll
        for (int i = 0; i < 8; i++)
            #pragma unroll
            for (int j = 0; j < 8; j++)
                sx[mblk * 2048 + (mrow * 8 + i) * 64 + ncol + 8 * j] = acc[i * 8 + j];
    }
    __syncthreads();

    float wsg = d_wsinv[0], wsu = d_wsinv[1];
    if (wid < 8) {
        // tensor epilogue: n in [0,64)
        #pragma unroll
        for (int mt = 0; mt < 2; mt++) {
            #pragma unroll
            for (int h2 = 0; h2 < 2; h2++) {
                int row = mb * 128 + (2 * wm + mt) * 16 + h2 * 8 + (lane >> 2);
                float ai = d_ainv[row];
                float sg = wsg * ai, su = wsu * ai;
                float* drow = d_h + (size_t)row * FDIM;
                #pragma unroll
                for (int j8 = 0; j8 < 4; j8++) {
                    int n0 = nb * 128 + (wn * 4 + j8) * 8 + 2 * (lane & 3);
                    float g0 = (float)acc[(mt * 4 + j8) * 4 + h2 * 2] * sg;
                    float g1 = (float)acc[(mt * 4 + j8) * 4 + h2 * 2 + 1] * sg;
                    float u0 = (float)acc[32 + (mt * 4 + j8) * 4 + h2 * 2] * su;
                    float u1 = (float)acc[32 + (mt * 4 + j8) * 4 + h2 * 2 + 1] * su;
                    float2 o;
                    o.x = g0 / (1.f + __expf(-g0)) * u0;
                    o.y = g1 / (1.f + __expf(-g1)) * u1;
                    *(float2*)(drow + n0) = o;
                }
            }
        }
    } else if (mat == 1) {
        // dp4a combine epilogue: n in [64,128)
        #pragma unroll
        for (int i = 0; i < 8; i++) {
            int row = mb * 128 + mblk * 32 + mrow * 8 + i;
            float ai = d_ainv[row];
            float sg = wsg * ai, su = wsu * ai;
            float* drow = d_h + (size_t)row * FDIM + nb * 128 + 64;
            #pragma unroll
            for (int j = 0; j < 8; j++) {
                float g = (float)sx[mblk * 2048 + (mrow * 8 + i) * 64 + ncol + 8 * j] * sg;
                float u = (float)acc[i * 8 + j] * su;
                drow[ncol + 8 * j] = g / (1.f + __expf(-g)) * u;
            }
        }
    }
}

// ---------------- K4: finalize Wd scale ----------------
__global__ void fin2_kernel() {
    int tid = threadIdx.x;
    double s = 0.0;
    for (int i = tid; i < 512; i += 256) s += (double)d_part[2 * 512 + i];
    #pragma unroll
    for (int o = 16; o; o >>= 1) s += __shfl_xor_sync(~0u, s, o);
    __shared__ double ds[8];
    if ((tid & 31) == 0) ds[tid >> 5] = s;
    __syncthreads();
    if (tid == 0) {
        double S = 0.0;
        #pragma unroll
        for (int k = 0; k < 8; k++) S += ds[k];
        d_wsinv[2] = (float)fmax(S / (double)WELEM, 1e-5);
    }
}

// ---------------- K5: v[f] = sum_d ternary(Wd[d,f]) ----------------
__global__ void vsum_kernel(const float* __restrict__ Wd) {
    int f = blockIdx.x * 256 + threadIdx.x;
    int d0 = blockIdx.y * 128;
    float ws = 1.0f / d_wsinv[2];
    float s = 0.f;
    #pragma unroll 4
    for (int d = 0; d < 128; d++)
        s += fminf(fmaxf(rintf(Wd[(size_t)(d0 + d) * FDIM + f] * ws), -1.f), 1.f);
    atomicAdd(&d_v[f], s);
}

// ---------------- K6: rmsnorm + act quant + dot with v ----------------
__global__ void hnorm_kernel(const float* __restrict__ lnw) {
    __shared__ float row[FDIM];
    __shared__ float red[8];
    __shared__ float bval;
    int t = blockIdx.x, tid = threadIdx.x;
    const float* src = d_h + (size_t)t * FDIM;
    float ss = 0.f;
    for (int i = tid; i < FDIM; i += 256) { float v = src[i]; row[i] = v; ss += v * v; }
    ss = wsum(ss);
    if ((tid & 31) == 0) red[tid >> 5] = ss;
    __syncthreads();
    if (tid == 0) {
        float S = 0.f;
        #pragma unroll
        for (int k = 0; k < 8; k++) S += red[k];
        bval = rsqrtf(S / (float)FDIM + 1e-6f);
    }
    __syncthreads();
    float rn = bval, mx = 0.f;
    for (int i = tid; i < FDIM; i += 256) {
        float v = row[i] * rn * lnw[i];
        row[i] = v;
        mx = fmaxf(mx, fabsf(v));
    }
    mx = wmax(mx);
    if ((tid & 31) == 0) red[tid >> 5] = mx;
    __syncthreads();
    if (tid == 0) {
        float M = 0.f;
        #pragma unroll
        for (int k = 0; k < 8; k++) M = fmaxf(M, red[k]);
        bval = fmaxf(M, 1e-5f);
    }
    __syncthreads();
    float clipv = bval, scale = 127.f / clipv, dot = 0.f;
    for (int i = tid; i < FDIM; i += 256) {
        float q = fminf(fmaxf(rintf(row[i] * scale), -128.f), 127.f);
        dot += q * d_v[i];
    }
    dot = wsum(dot);
    if ((tid & 31) == 0) red[tid >> 5] = dot;
    __syncthreads();
    if (tid == 0) {
        float S = 0.f;
        #pragma unroll
        for (int k = 0; k < 8; k++) S += red[k];
        d_tok[t] = S * (clipv / 127.f) * d_wsinv[2];
    }
}

// ---------------- K7: pool ----------------
__global__ void pool_kernel() {
    int g = blockIdx.x, tid = threadIdx.x;
    float v = d_tok[g * 128 + tid];
    v = wsum(v);
    __shared__ float r[4];
    if ((tid & 31) == 0) r[tid >> 5] = v;
    __syncthreads();
    if (tid == 0) d_pool[g] = (r[0] + r[1] + r[2] + r[3]) * (1.0f / (128.f * 2048.f));
}

// ---------------- K8: classifier ----------------
__global__ void cls_kernel(const float* __restrict__ W, const float* __restrict__ b,
                           float* __restrict__ out) {
    int i = blockIdx.x * 256 + threadIdx.x;
    if (i < 8000) {
        int bb = i / 1000, n = i % 1000;
        float s = b[n];
        #pragma unroll
        for (int c = 0; c < 3; c++) s += d_pool[bb * 3 + c] * W[n * 3 + c];
        out[i] = s;
    }
}

extern "C" void kernel_launch(void* const* d_in, const int* in_sizes, int n_in,
                              void* d_out, int out_size) {
    const float* x    = (const float*)d_in[0];
    const float* Wg   = (const float*)d_in[1];
    const float* Wu   = (const float*)d_in[2];
    const float* Wd   = (const float*)d_in[3];
    const float* lnw  = (const float*)d_in[4];
    const float* clsW = (const float*)d_in[5];
    const float* clsb = (const float*)d_in[6];
    float* out = (float*)d_out;

    cudaFuncSetAttribute(gemm_kernel, cudaFuncAttributeMaxDynamicSharedMemorySize, SMEM_GEMM);

    wred_kernel<<<dim3(512, 3), 256>>>(Wg, Wu, Wd);
    qw2_kernel<<<dim3(4096, 2), 256>>>(Wg, Wu);
    act_kernel<<<TOK, 256>>>(x);
    gemm_kernel<<<dim3(FDIM / BN, TOK / BM), 512, SMEM_GEMM>>>();
    fin2_kernel<<<1, 256>>>();
    vsum_kernel<<<dim3(32, 16), 256>>>(Wd);
    hnorm_kernel<<<TOK, 256>>>(lnw);
    pool_kernel<<<24, 128>>>();
    cls_kernel<<<32, 256>>>(clsW, clsb, out);
}